// round 5
// baseline (speedup 1.0000x reference)
#include <cuda_runtime.h>
#include <math.h>

#define BB 4
#define NN 262144
#define KK 6000
#define NPAD 6016            // 94 * 64
#define NW 94                // 64-bit words per row
#define CAP 16384            // candidate capacity (power of 2 for bitonic)
#define PROP 1000
#define THR 0.7f

// ---------------- scratch (static device globals; no allocation) ----------------
__device__ unsigned int       d_hist[BB][65536];
__device__ int                d_P[BB];
__device__ unsigned int       d_candCount[BB];
__device__ unsigned long long d_cand[BB][CAP];
__device__ float4             d_boxes[BB][NPAD];
__device__ unsigned long long d_mask[BB][NPAD][NW];
__device__ unsigned long long d_rowAny[BB][NW];

// ---------------- init: zero per-launch state ----------------
__global__ void k_init() {
    int i = blockIdx.x * blockDim.x + threadIdx.x;
    if (i < BB * 65536) ((unsigned int*)d_hist)[i] = 0u;
    if (i < BB)          d_candCount[i] = 0u;
    if (i < BB * NW)     ((unsigned long long*)d_rowAny)[i] = 0ull;
}

// ---------------- histogram of fg-score top-16 bits ----------------
__global__ void k_hist(const float* __restrict__ scores) {
    int i = blockIdx.x * blockDim.x + threadIdx.x;   // over BB*NN
    if (i >= BB * NN) return;
    unsigned int bits = __float_as_uint(scores[2 * i + 1]);  // scores in [0,1): positive
    int b = i >> 18;                                 // NN = 2^18
    atomicAdd(&d_hist[b][bits >> 16], 1u);
}

// ---------------- find 16-bit prefix threshold (descending cumsum crosses KK) ----
__global__ void k_thresh() {
    int b = blockIdx.x, t = threadIdx.x;             // 1024 threads
    __shared__ unsigned int csum[1024];
    const unsigned int* h = d_hist[b];
    unsigned int s = 0;
    int base = t * 64;
    #pragma unroll 8
    for (int kk = 0; kk < 64; ++kk) s += h[base + kk];
    csum[t] = s;
    __syncthreads();
    if (t == 0) {
        unsigned int tot = 0;
        int c = 1023;
        for (; c > 0; --c) {
            if (tot + csum[c] >= (unsigned)KK) break;
            tot += csum[c];
        }
        int P = 0;
        unsigned int tot2 = tot;
        for (int kk = 63; kk >= 0; --kk) {
            unsigned int hv = h[c * 64 + kk];
            if (tot2 + hv >= (unsigned)KK) { P = c * 64 + kk; break; }
            tot2 += hv;
        }
        d_P[b] = P;
    }
}

// ---------------- gather candidate keys: (score_bits<<32)|(~idx) ----------------
__global__ void k_gather(const float* __restrict__ scores) {
    int i = blockIdx.x * blockDim.x + threadIdx.x;
    if (i >= BB * NN) return;
    unsigned int bits = __float_as_uint(scores[2 * i + 1]);
    int b = i >> 18;
    int n = i & (NN - 1);
    if ((int)(bits >> 16) >= d_P[b]) {
        unsigned int pos = atomicAdd(&d_candCount[b], 1u);
        if (pos < CAP)
            d_cand[b][pos] = ((unsigned long long)bits << 32) |
                             (unsigned long long)(0xFFFFFFFFu - (unsigned)n);
    }
}

// ---------------- bitonic sort (desc) + decode top-K + box delta + clip --------
__global__ void k_sortbox(const float* __restrict__ deltas,
                          const float* __restrict__ anchors) {
    extern __shared__ unsigned long long skey[];     // CAP entries = 128 KB
    int b = blockIdx.x, t = threadIdx.x;             // 1024 threads
    unsigned int cnt = d_candCount[b];
    if (cnt > CAP) cnt = CAP;
    for (int i = t; i < CAP; i += 1024)
        skey[i] = (i < (int)cnt) ? d_cand[b][i] : 0ull;
    __syncthreads();

    for (int k = 2; k <= CAP; k <<= 1) {
        for (int j = k >> 1; j > 0; j >>= 1) {
            for (int i = t; i < CAP; i += 1024) {
                int p = i ^ j;
                if (p > i) {
                    unsigned long long a = skey[i], c = skey[p];
                    bool up = (i & k) == 0;          // descending sort
                    if (up ? (a < c) : (a > c)) { skey[i] = c; skey[p] = a; }
                }
            }
            __syncthreads();
        }
    }

    const float4* anc4 = (const float4*)anchors;
    const float4* del4 = (const float4*)deltas;
    for (int r = t; r < NPAD; r += 1024) {
        float4 box = make_float4(0.f, 0.f, 0.f, 0.f);
        if (r < KK) {
            unsigned long long key = skey[r];
            unsigned int n = 0xFFFFFFFFu - (unsigned int)(key & 0xFFFFFFFFull);
            float4 a4 = anc4[(size_t)b * NN + n];
            float4 dd = del4[(size_t)b * NN + n];
            float d0 = __fmul_rn(dd.x, 0.1f);
            float d1 = __fmul_rn(dd.y, 0.1f);
            float d2 = __fmul_rn(dd.z, 0.2f);
            float d3 = __fmul_rn(dd.w, 0.2f);
            float w  = __fsub_rn(a4.z, a4.x);
            float h  = __fsub_rn(a4.w, a4.y);
            float cx = __fadd_rn(a4.x, __fmul_rn(0.5f, w));
            float cy = __fadd_rn(a4.y, __fmul_rn(0.5f, h));
            cx = __fadd_rn(cx, __fmul_rn(d0, w));
            cy = __fadd_rn(cy, __fmul_rn(d1, h));
            w  = __fmul_rn(w, (float)exp((double)d2));
            h  = __fmul_rn(h, (float)exp((double)d3));
            float x1 = __fsub_rn(cx, __fmul_rn(0.5f, w));
            float y1 = __fsub_rn(cy, __fmul_rn(0.5f, h));
            float x2 = __fadd_rn(cx, __fmul_rn(0.5f, w));
            float y2 = __fadd_rn(cy, __fmul_rn(0.5f, h));
            box.x = fminf(fmaxf(x1, 0.f), 1.f);
            box.y = fminf(fmaxf(y1, 0.f), 1.f);
            box.z = fminf(fmaxf(x2, 0.f), 1.f);
            box.w = fminf(fmaxf(y2, 0.f), 1.f);
        }
        d_boxes[b][r] = box;
    }
}

// ---------------- suppression bitmask (upper triangle) -------------------------
__global__ void k_mask() {
    int cb = blockIdx.x, rb = blockIdx.y, b = blockIdx.z;
    if (cb < rb) return;
    __shared__ float4 cbox[64];
    int t = threadIdx.x;
    cbox[t] = d_boxes[b][cb * 64 + t];
    __syncthreads();
    int i = rb * 64 + t;
    float4 bx = d_boxes[b][i];
    float areaI = __fmul_rn(__fsub_rn(bx.z, bx.x), __fsub_rn(bx.w, bx.y));
    unsigned long long bits = 0ull;
    #pragma unroll 4
    for (int c = 0; c < 64; ++c) {
        int j = cb * 64 + c;
        if (j > i) {
            float4 o = cbox[c];
            float lx = fmaxf(bx.x, o.x), ly = fmaxf(bx.y, o.y);
            float rx = fminf(bx.z, o.z), ry = fminf(bx.w, o.w);
            float iw = fmaxf(__fsub_rn(rx, lx), 0.f);
            float ih = fmaxf(__fsub_rn(ry, ly), 0.f);
            float inter = __fmul_rn(iw, ih);
            float areaJ = __fmul_rn(__fsub_rn(o.z, o.x), __fsub_rn(o.w, o.y));
            float denom = __fadd_rn(__fsub_rn(__fadd_rn(areaI, areaJ), inter), 1e-12f);
            float iou = __fdiv_rn(inter, denom);
            if (iou > THR) bits |= (1ull << c);
        }
    }
    d_mask[b][i][cb] = bits;
    if (bits) atomicOr(&d_rowAny[b][i >> 6], 1ull << (i & 63));
}

// ---------------- single-warp greedy scan + output -----------------------------
__global__ void k_scan(float* __restrict__ out) {
    int b = blockIdx.x, lane = threadIdx.x;          // 32 threads
    __shared__ unsigned long long remv[NW];
    __shared__ unsigned long long rowAnyS[NW];
    __shared__ int keepIdx[PROP];
    for (int w = lane; w < NW; w += 32) {
        remv[w] = 0ull;
        rowAnyS[w] = d_rowAny[b][w];
    }
    __syncwarp();

    int kept = 0;
    for (int w = 0; w < NW && kept < PROP; ++w) {
        unsigned long long remWord = remv[w];
        unsigned long long rw = rowAnyS[w];
        int lim = (w * 64 + 64 <= KK) ? 64 : (KK - w * 64);
        for (int bit = 0; bit < lim; ++bit) {
            if (!((remWord >> bit) & 1ull)) {
                int i = w * 64 + bit;
                if (lane == 0) keepIdx[kept] = i;
                kept++;
                if (kept == PROP) break;
                if ((rw >> bit) & 1ull) {
                    const unsigned long long* row = d_mask[b][i];
                    for (int ww = w + lane; ww < NW; ww += 32)
                        remv[ww] |= row[ww];
                    __syncwarp();
                    remWord = remv[w];
                }
            }
        }
    }
    __syncwarp();

    int total = kept;
    float4* o4 = (float4*)(out + (size_t)b * PROP * 4);
    for (int r = lane; r < PROP; r += 32) {
        float4 v = make_float4(0.f, 0.f, 0.f, 0.f);
        if (r < total) v = d_boxes[b][keepIdx[r]];
        o4[r] = v;
    }
}

// ---------------- launch ----------------
extern "C" void kernel_launch(void* const* d_in, const int* in_sizes, int n_in,
                              void* d_out, int out_size) {
    const float* scores  = (const float*)d_in[0];
    const float* deltas  = (const float*)d_in[1];
    const float* anchors = (const float*)d_in[2];
    float* out = (float*)d_out;

    cudaFuncSetAttribute(k_sortbox, cudaFuncAttributeMaxDynamicSharedMemorySize,
                         CAP * (int)sizeof(unsigned long long));

    k_init  <<<(BB * 65536 + 255) / 256, 256>>>();
    k_hist  <<<(BB * NN + 255) / 256, 256>>>(scores);
    k_thresh<<<BB, 1024>>>();
    k_gather<<<(BB * NN + 255) / 256, 256>>>(scores);
    k_sortbox<<<BB, 1024, CAP * (int)sizeof(unsigned long long)>>>(deltas, anchors);
    k_mask  <<<dim3(NW, NW, BB), 64>>>();
    k_scan  <<<BB, 32>>>(out);
}

// round 6
// speedup vs baseline: 2.1960x; 2.1960x over previous
#include <cuda_runtime.h>
#include <math.h>

#define BB 4
#define NN 262144
#define KK 6000
#define NPAD 6016            // 94 * 64
#define NW 94                // 64-bit words per full row
#define CAP 8192             // candidate capacity (power of 2 for bitonic)
#define PROP 1000
#define THR 0.7f
#define C1 2048              // phase-1 NMS window (rows/cols)
#define NW1 32               // 64-bit words for phase-1 row

// ---------------- scratch (static device globals; no allocation) ----------------
__device__ unsigned int       d_hist[BB][65536];
__device__ int                d_P[BB];
__device__ unsigned int       d_candCount[BB];
__device__ unsigned long long d_cand[BB][CAP];
__device__ float4             d_boxes[BB][NPAD];
__device__ unsigned long long d_mask[BB][NPAD][NW];
__device__ unsigned long long d_rowAny[BB][NW];
__device__ int                d_done[BB];

// ---------------- init: zero per-launch state ----------------
__global__ void k_init() {
    int i = blockIdx.x * blockDim.x + threadIdx.x;
    if (i < BB * 65536) ((unsigned int*)d_hist)[i] = 0u;
    if (i < BB)        { d_candCount[i] = 0u; d_done[i] = 0; }
    if (i < BB * NW)     ((unsigned long long*)d_rowAny)[i] = 0ull;
}

// ---------------- histogram of fg-score top-16 bits ----------------
__global__ void k_hist(const float* __restrict__ scores) {
    int i = blockIdx.x * blockDim.x + threadIdx.x;   // over BB*NN
    if (i >= BB * NN) return;
    unsigned int bits = __float_as_uint(scores[2 * i + 1]);  // scores in [0,1): positive
    int b = i >> 18;                                 // NN = 2^18
    atomicAdd(&d_hist[b][bits >> 16], 1u);
}

// ---------------- find 16-bit prefix threshold (descending cumsum crosses KK) ----
__global__ void k_thresh() {
    int b = blockIdx.x, t = threadIdx.x;             // 1024 threads
    __shared__ unsigned int csum[1024];
    const unsigned int* h = d_hist[b];
    unsigned int s = 0;
    int base = t * 64;
    #pragma unroll 8
    for (int kk = 0; kk < 64; ++kk) s += h[base + kk];
    csum[t] = s;
    __syncthreads();
    if (t == 0) {
        unsigned int tot = 0;
        int c = 1023;
        for (; c > 0; --c) {
            if (tot + csum[c] >= (unsigned)KK) break;
            tot += csum[c];
        }
        int P = 0;
        unsigned int tot2 = tot;
        for (int kk = 63; kk >= 0; --kk) {
            unsigned int hv = h[c * 64 + kk];
            if (tot2 + hv >= (unsigned)KK) { P = c * 64 + kk; break; }
            tot2 += hv;
        }
        d_P[b] = P;
    }
}

// ---------------- gather candidate keys: (score_bits<<32)|(~idx) ----------------
__global__ void k_gather(const float* __restrict__ scores) {
    int i = blockIdx.x * blockDim.x + threadIdx.x;
    if (i >= BB * NN) return;
    unsigned int bits = __float_as_uint(scores[2 * i + 1]);
    int b = i >> 18;
    int n = i & (NN - 1);
    if ((int)(bits >> 16) >= d_P[b]) {
        unsigned int pos = atomicAdd(&d_candCount[b], 1u);
        if (pos < CAP)
            d_cand[b][pos] = ((unsigned long long)bits << 32) |
                             (unsigned long long)(0xFFFFFFFFu - (unsigned)n);
    }
}

// ---------------- bitonic sort (desc) + decode top-K + box delta + clip --------
__global__ void k_sortbox(const float* __restrict__ deltas,
                          const float* __restrict__ anchors) {
    extern __shared__ unsigned long long skey[];     // CAP entries = 64 KB
    int b = blockIdx.x, t = threadIdx.x;             // 1024 threads
    unsigned int cnt = d_candCount[b];
    if (cnt > CAP) cnt = CAP;
    for (int i = t; i < CAP; i += 1024)
        skey[i] = (i < (int)cnt) ? d_cand[b][i] : 0ull;
    __syncthreads();

    for (int k = 2; k <= CAP; k <<= 1) {
        for (int j = k >> 1; j > 0; j >>= 1) {
            for (int i = t; i < CAP; i += 1024) {
                int p = i ^ j;
                if (p > i) {
                    unsigned long long a = skey[i], c = skey[p];
                    bool up = (i & k) == 0;          // descending sort
                    if (up ? (a < c) : (a > c)) { skey[i] = c; skey[p] = a; }
                }
            }
            __syncthreads();
        }
    }

    const float4* anc4 = (const float4*)anchors;
    const float4* del4 = (const float4*)deltas;
    for (int r = t; r < NPAD; r += 1024) {
        float4 box = make_float4(0.f, 0.f, 0.f, 0.f);
        if (r < KK) {
            unsigned long long key = skey[r];
            unsigned int n = 0xFFFFFFFFu - (unsigned int)(key & 0xFFFFFFFFull);
            float4 a4 = anc4[(size_t)b * NN + n];
            float4 dd = del4[(size_t)b * NN + n];
            float d0 = __fmul_rn(dd.x, 0.1f);
            float d1 = __fmul_rn(dd.y, 0.1f);
            float d2 = __fmul_rn(dd.z, 0.2f);
            float d3 = __fmul_rn(dd.w, 0.2f);
            float w  = __fsub_rn(a4.z, a4.x);
            float h  = __fsub_rn(a4.w, a4.y);
            float cx = __fadd_rn(a4.x, __fmul_rn(0.5f, w));
            float cy = __fadd_rn(a4.y, __fmul_rn(0.5f, h));
            cx = __fadd_rn(cx, __fmul_rn(d0, w));
            cy = __fadd_rn(cy, __fmul_rn(d1, h));
            w  = __fmul_rn(w, (float)exp((double)d2));
            h  = __fmul_rn(h, (float)exp((double)d3));
            float x1 = __fsub_rn(cx, __fmul_rn(0.5f, w));
            float y1 = __fsub_rn(cy, __fmul_rn(0.5f, h));
            float x2 = __fadd_rn(cx, __fmul_rn(0.5f, w));
            float y2 = __fadd_rn(cy, __fmul_rn(0.5f, h));
            box.x = fminf(fmaxf(x1, 0.f), 1.f);
            box.y = fminf(fmaxf(y1, 0.f), 1.f);
            box.z = fminf(fmaxf(x2, 0.f), 1.f);
            box.w = fminf(fmaxf(y2, 0.f), 1.f);
        }
        d_boxes[b][r] = box;
    }
}

// ---------------- shared IoU block body ---------------------------------------
__device__ __forceinline__ void mask_block_body(int cb, int rb, int b) {
    __shared__ float4 cbox[64];
    __shared__ float  cArea[64];
    int t = threadIdx.x;
    float4 c4 = d_boxes[b][cb * 64 + t];
    cbox[t] = c4;
    cArea[t] = __fmul_rn(__fsub_rn(c4.z, c4.x), __fsub_rn(c4.w, c4.y));
    __syncthreads();
    int i = rb * 64 + t;
    float4 bx = d_boxes[b][i];
    float areaI = __fmul_rn(__fsub_rn(bx.z, bx.x), __fsub_rn(bx.w, bx.y));
    bool diag = (cb == rb);
    unsigned long long bits = 0ull;
    #pragma unroll 4
    for (int c = 0; c < 64; ++c) {
        if (!diag || c > t) {
            float4 o = cbox[c];
            float lx = fmaxf(bx.x, o.x), ly = fmaxf(bx.y, o.y);
            float rx = fminf(bx.z, o.z), ry = fminf(bx.w, o.w);
            float iw = fmaxf(__fsub_rn(rx, lx), 0.f);
            float ih = fmaxf(__fsub_rn(ry, ly), 0.f);
            float inter = __fmul_rn(iw, ih);
            float denom = __fadd_rn(__fsub_rn(__fadd_rn(areaI, cArea[c]), inter), 1e-12f);
            float iou = __fdiv_rn(inter, denom);
            if (iou > THR) bits |= (1ull << c);
        }
    }
    d_mask[b][i][cb] = bits;
    if (bits) atomicOr(&d_rowAny[b][i >> 6], 1ull << (i & 63));
}

// ---------------- phase-1 mask: top C1 x C1 triangle --------------------------
__global__ void k_mask1() {
    int cb = blockIdx.x, rb = blockIdx.y, b = blockIdx.z;
    if (cb < rb) return;
    mask_block_body(cb, rb, b);
}

// ---------------- phase-2 mask (fallback, gated per batch) --------------------
__global__ void k_mask2() {
    int cb = blockIdx.x, rb = blockIdx.y, b = blockIdx.z;
    if (d_done[b]) return;
    if (cb < rb) return;
    if (cb < NW1 && rb < NW1) return;   // phase 1 already wrote this region
    mask_block_body(cb, rb, b);
}

// ---------------- phase-1 scan: greedy NMS over first C1 boxes ----------------
__global__ void k_scan1(float* __restrict__ out) {
    int b = blockIdx.x, lane = threadIdx.x;          // 32 threads
    __shared__ unsigned long long remv[NW1];
    __shared__ unsigned long long rowAnyS[NW1];
    __shared__ int keepIdx[PROP];
    for (int w = lane; w < NW1; w += 32) {
        remv[w] = 0ull;
        rowAnyS[w] = d_rowAny[b][w];
    }
    __syncwarp();

    int kept = 0;
    for (int w = 0; w < NW1 && kept < PROP; ++w) {
        unsigned long long remWord = remv[w];
        unsigned long long rw = rowAnyS[w];
        for (int bit = 0; bit < 64; ++bit) {
            if (!((remWord >> bit) & 1ull)) {
                int i = w * 64 + bit;
                if (lane == 0) keepIdx[kept] = i;
                kept++;
                if (kept == PROP) break;
                if ((rw >> bit) & 1ull) {
                    const unsigned long long* row = d_mask[b][i];
                    for (int ww = w + lane; ww < NW1; ww += 32)
                        remv[ww] |= row[ww];
                    __syncwarp();
                    remWord = remv[w];
                }
            }
        }
    }
    __syncwarp();

    if (kept == PROP) {
        if (lane == 0) d_done[b] = 1;
        float4* o4 = (float4*)(out + (size_t)b * PROP * 4);
        for (int r = lane; r < PROP; r += 32)
            o4[r] = d_boxes[b][keepIdx[r]];
    }
}

// ---------------- phase-2 scan (fallback, gated per batch) --------------------
__global__ void k_scan2(float* __restrict__ out) {
    int b = blockIdx.x, lane = threadIdx.x;          // 32 threads
    if (d_done[b]) return;
    __shared__ unsigned long long remv[NW];
    __shared__ unsigned long long rowAnyS[NW];
    __shared__ int keepIdx[PROP];
    for (int w = lane; w < NW; w += 32) {
        remv[w] = 0ull;
        rowAnyS[w] = d_rowAny[b][w];
    }
    __syncwarp();

    int kept = 0;
    for (int w = 0; w < NW && kept < PROP; ++w) {
        unsigned long long remWord = remv[w];
        unsigned long long rw = rowAnyS[w];
        int lim = (w * 64 + 64 <= KK) ? 64 : (KK - w * 64);
        for (int bit = 0; bit < lim; ++bit) {
            if (!((remWord >> bit) & 1ull)) {
                int i = w * 64 + bit;
                if (lane == 0) keepIdx[kept] = i;
                kept++;
                if (kept == PROP) break;
                if ((rw >> bit) & 1ull) {
                    const unsigned long long* row = d_mask[b][i];
                    for (int ww = w + lane; ww < NW; ww += 32)
                        remv[ww] |= row[ww];
                    __syncwarp();
                    remWord = remv[w];
                }
            }
        }
    }
    __syncwarp();

    int total = kept;
    float4* o4 = (float4*)(out + (size_t)b * PROP * 4);
    for (int r = lane; r < PROP; r += 32) {
        float4 v = make_float4(0.f, 0.f, 0.f, 0.f);
        if (r < total) v = d_boxes[b][keepIdx[r]];
        o4[r] = v;
    }
}

// ---------------- launch ----------------
extern "C" void kernel_launch(void* const* d_in, const int* in_sizes, int n_in,
                              void* d_out, int out_size) {
    const float* scores  = (const float*)d_in[0];
    const float* deltas  = (const float*)d_in[1];
    const float* anchors = (const float*)d_in[2];
    float* out = (float*)d_out;

    cudaFuncSetAttribute(k_sortbox, cudaFuncAttributeMaxDynamicSharedMemorySize,
                         CAP * (int)sizeof(unsigned long long));

    k_init  <<<(BB * 65536 + 255) / 256, 256>>>();
    k_hist  <<<(BB * NN + 255) / 256, 256>>>(scores);
    k_thresh<<<BB, 1024>>>();
    k_gather<<<(BB * NN + 255) / 256, 256>>>(scores);
    k_sortbox<<<BB, 1024, CAP * (int)sizeof(unsigned long long)>>>(deltas, anchors);
    k_mask1 <<<dim3(NW1, NW1, BB), 64>>>();
    k_scan1 <<<BB, 32>>>(out);
    k_mask2 <<<dim3(NW, NW, BB), 64>>>();
    k_scan2 <<<BB, 32>>>(out);
}

// round 7
// speedup vs baseline: 3.0192x; 1.3749x over previous
#include <cuda_runtime.h>
#include <math.h>

#define BB 4
#define NN 262144
#define KK 6000
#define NPAD 6016            // 94 * 64
#define NW 94                // 64-bit words per full row
#define SCAPACITY 8192       // sorted-candidate capacity
#define PROP 1000
#define THR 0.7f
#define C1 2048              // phase-1 NMS window (rows/cols)
#define NW1 32               // 64-bit words for phase-1 row
#define GCAP 2048            // per-prefix-bin group sort capacity
#define RCAP 320             // cached suppressor rows in scan1

// ---------------- scratch (static device globals; no allocation) ----------------
__device__ unsigned int       d_hist[BB][65536];
__device__ int                d_base[BB][65536];
__device__ int                d_P[BB];
__device__ unsigned long long d_sorted[BB][SCAPACITY];
__device__ float4             d_boxes[BB][NPAD];
__device__ unsigned long long d_mask[BB][NPAD][NW];
__device__ unsigned long long d_rowAny[BB][NW];
__device__ int                d_done[BB];

// ---------------- init: zero per-launch state ----------------
__global__ void k_init() {
    int i = blockIdx.x * blockDim.x + threadIdx.x;
    if (i < BB * 65536) ((unsigned int*)d_hist)[i] = 0u;
    if (i < BB)        { d_P[i] = 0; d_done[i] = 0; }
    if (i < BB * NW)     ((unsigned long long*)d_rowAny)[i] = 0ull;
}

// ---------------- histogram of fg-score top-16 bits (float4 vectorized) --------
__global__ void k_hist(const float4* __restrict__ s4) {
    int t = blockIdx.x * blockDim.x + threadIdx.x;   // over BB*NN/4
    if (t >= BB * NN / 4) return;
    float4 a = s4[2 * t], c = s4[2 * t + 1];         // 4 [bg,fg] pairs
    int b = t >> 16;                                 // (4t) >> 18
    atomicAdd(&d_hist[b][__float_as_uint(a.y) >> 16], 1u);
    atomicAdd(&d_hist[b][__float_as_uint(a.w) >> 16], 1u);
    atomicAdd(&d_hist[b][__float_as_uint(c.y) >> 16], 1u);
    atomicAdd(&d_hist[b][__float_as_uint(c.w) >> 16], 1u);
}

// ---------------- suffix-scan of histogram -> exact slot bases + threshold -----
__global__ void k_base() {
    int b = blockIdx.x, t = threadIdx.x;             // 1024 threads
    __shared__ unsigned int part[1024];
    const unsigned int* h = d_hist[b];
    int base0 = t * 64;
    unsigned int mySum = 0;
    #pragma unroll 8
    for (int kk = 0; kk < 64; ++kk) mySum += h[base0 + kk];
    part[t] = mySum;
    __syncthreads();
    for (int off = 1; off < 1024; off <<= 1) {       // inclusive suffix scan
        unsigned int v = (t + off < 1024) ? part[t + off] : 0u;
        __syncthreads();
        part[t] += v;
        __syncthreads();
    }
    unsigned int acc = part[t] - mySum;              // count of prefix > my chunk
    int bestBin = -1;
    for (int kk = 63; kk >= 0; --kk) {
        int bin = base0 + kk;
        unsigned int hv = h[bin];
        d_base[b][bin] = (int)acc;                   // count strictly above bin
        if (bestBin < 0 && acc + hv >= (unsigned)KK) bestBin = bin;
        acc += hv;
    }
    if (bestBin >= 0) atomicMax(&d_P[b], bestBin);
}

// ---------------- scatter candidates into exact bin slot ranges ----------------
__global__ void k_scatter(const float4* __restrict__ s4) {
    int t = blockIdx.x * blockDim.x + threadIdx.x;   // over BB*NN/4
    if (t >= BB * NN / 4) return;
    float4 a = s4[2 * t], c = s4[2 * t + 1];
    int b = t >> 16;
    int P = d_P[b];
    int pair0 = (4 * t) & (NN - 1);
    float fg[4] = {a.y, a.w, c.y, c.w};
    #pragma unroll
    for (int j = 0; j < 4; ++j) {
        unsigned int bits = __float_as_uint(fg[j]);
        if ((int)(bits >> 16) >= P) {
            int pos = atomicAdd(&d_base[b][bits >> 16], 1);
            if (pos < SCAPACITY)
                d_sorted[b][pos] = ((unsigned long long)bits << 32) |
                                   (unsigned long long)(0xFFFFFFFFu - (unsigned)(pair0 + j));
        }
    }
}

// ---------------- per-bin group sort (bitonic 2048, one block per active bin) --
__global__ void k_groupsort() {
    __shared__ unsigned long long skey[GCAP];        // 16 KB
    int b = blockIdx.y;
    int bin = d_P[b] + blockIdx.x;
    if (bin > 65535) return;
    int hv = (int)d_hist[b][bin];
    if (hv <= 1) return;
    int end = d_base[b][bin];                        // post-scatter = orig + hist
    int start = end - hv;
    int g = hv < GCAP ? hv : GCAP;
    if (end > SCAPACITY) end = SCAPACITY;
    int t = threadIdx.x;                             // 1024 threads
    for (int i = t; i < GCAP; i += 1024)
        skey[i] = (i < g && start + i < SCAPACITY) ? d_sorted[b][start + i] : 0ull;
    __syncthreads();
    for (int k = 2; k <= GCAP; k <<= 1) {
        for (int j = k >> 1; j > 0; j >>= 1) {
            for (int i = t; i < GCAP; i += 1024) {
                int p = i ^ j;
                if (p > i) {
                    unsigned long long x = skey[i], y = skey[p];
                    bool up = (i & k) == 0;          // descending
                    if (up ? (x < y) : (x > y)) { skey[i] = y; skey[p] = x; }
                }
            }
            __syncthreads();
        }
    }
    for (int i = t; i < g; i += 1024)
        if (start + i < SCAPACITY) d_sorted[b][start + i] = skey[i];
}

// ---------------- decode sorted keys -> boxes (fully parallel) -----------------
__global__ void k_box(const float* __restrict__ deltas,
                      const float* __restrict__ anchors) {
    int i = blockIdx.x * blockDim.x + threadIdx.x;   // over BB*NPAD
    if (i >= BB * NPAD) return;
    int b = i / NPAD;
    int r = i - b * NPAD;
    float4 box = make_float4(0.f, 0.f, 0.f, 0.f);
    if (r < KK) {
        unsigned long long key = d_sorted[b][r];
        unsigned int n = 0xFFFFFFFFu - (unsigned int)(key & 0xFFFFFFFFull);
        const float4* anc4 = (const float4*)anchors;
        const float4* del4 = (const float4*)deltas;
        float4 a4 = anc4[(size_t)b * NN + n];
        float4 dd = del4[(size_t)b * NN + n];
        float d0 = __fmul_rn(dd.x, 0.1f);
        float d1 = __fmul_rn(dd.y, 0.1f);
        float d2 = __fmul_rn(dd.z, 0.2f);
        float d3 = __fmul_rn(dd.w, 0.2f);
        float w  = __fsub_rn(a4.z, a4.x);
        float h  = __fsub_rn(a4.w, a4.y);
        float cx = __fadd_rn(a4.x, __fmul_rn(0.5f, w));
        float cy = __fadd_rn(a4.y, __fmul_rn(0.5f, h));
        cx = __fadd_rn(cx, __fmul_rn(d0, w));
        cy = __fadd_rn(cy, __fmul_rn(d1, h));
        w  = __fmul_rn(w, (float)exp((double)d2));
        h  = __fmul_rn(h, (float)exp((double)d3));
        float x1 = __fsub_rn(cx, __fmul_rn(0.5f, w));
        float y1 = __fsub_rn(cy, __fmul_rn(0.5f, h));
        float x2 = __fadd_rn(cx, __fmul_rn(0.5f, w));
        float y2 = __fadd_rn(cy, __fmul_rn(0.5f, h));
        box.x = fminf(fmaxf(x1, 0.f), 1.f);
        box.y = fminf(fmaxf(y1, 0.f), 1.f);
        box.z = fminf(fmaxf(x2, 0.f), 1.f);
        box.w = fminf(fmaxf(y2, 0.f), 1.f);
    }
    d_boxes[b][r] = box;
}

// ---------------- shared IoU block body ---------------------------------------
__device__ __forceinline__ void mask_block_body(int cb, int rb, int b) {
    __shared__ float4 cbox[64];
    __shared__ float  cArea[64];
    int t = threadIdx.x;
    float4 c4 = d_boxes[b][cb * 64 + t];
    cbox[t] = c4;
    cArea[t] = __fmul_rn(__fsub_rn(c4.z, c4.x), __fsub_rn(c4.w, c4.y));
    __syncthreads();
    int i = rb * 64 + t;
    float4 bx = d_boxes[b][i];
    float areaI = __fmul_rn(__fsub_rn(bx.z, bx.x), __fsub_rn(bx.w, bx.y));
    bool diag = (cb == rb);
    unsigned long long bits = 0ull;
    #pragma unroll 4
    for (int c = 0; c < 64; ++c) {
        if (!diag || c > t) {
            float4 o = cbox[c];
            float lx = fmaxf(bx.x, o.x), ly = fmaxf(bx.y, o.y);
            float rx = fminf(bx.z, o.z), ry = fminf(bx.w, o.w);
            float iw = fmaxf(__fsub_rn(rx, lx), 0.f);
            float ih = fmaxf(__fsub_rn(ry, ly), 0.f);
            float inter = __fmul_rn(iw, ih);
            float denom = __fadd_rn(__fsub_rn(__fadd_rn(areaI, cArea[c]), inter), 1e-12f);
            float iou = __fdiv_rn(inter, denom);
            if (iou > THR) bits |= (1ull << c);
        }
    }
    d_mask[b][i][cb] = bits;
    if (bits) atomicOr(&d_rowAny[b][i >> 6], 1ull << (i & 63));
}

// ---------------- phase-1 mask: top C1 x C1 triangle --------------------------
__global__ void k_mask1() {
    int cb = blockIdx.x, rb = blockIdx.y, b = blockIdx.z;
    if (cb < rb) return;
    mask_block_body(cb, rb, b);
}

// ---------------- phase-2 mask (fallback, gated per batch) --------------------
__global__ void k_mask2() {
    int cb = blockIdx.x, rb = blockIdx.y, b = blockIdx.z;
    if (d_done[b]) return;
    if (cb < rb) return;
    if (cb < NW1 && rb < NW1) return;   // phase 1 already wrote this region
    mask_block_body(cb, rb, b);
}

// ---------------- phase-1 scan: cache suppressor rows, then greedy NMS --------
__global__ void k_scan1(float* __restrict__ out) {
    int b = blockIdx.x, t = threadIdx.x;             // 1024 threads
    extern __shared__ unsigned long long cache[];    // RCAP*32 words = 80 KB
    __shared__ unsigned long long remv[NW1];
    __shared__ unsigned long long rowAnyS[NW1];
    __shared__ int keepIdx[PROP];
    __shared__ short slotv[C1];
    __shared__ int rowOf[RCAP];
    __shared__ int nsup, keptS;
    if (t == 0) { nsup = 0; keptS = 0; }
    if (t < NW1) { remv[t] = 0ull; rowAnyS[t] = d_rowAny[b][t]; }
    __syncthreads();

    // compact suppressor rows
    for (int i = t; i < C1; i += 1024) {
        short s = -1;
        if ((rowAnyS[i >> 6] >> (i & 63)) & 1ull) {
            int p = atomicAdd(&nsup, 1);
            if (p < RCAP) { s = (short)p; rowOf[p] = i; }
        }
        slotv[i] = s;
    }
    __syncthreads();

    // bulk-load cached rows (high MLP)
    int ns = nsup < RCAP ? nsup : RCAP;
    for (int w = t; w < ns * 32; w += 1024) {
        int s = w >> 5, ww = w & 31;
        cache[s * 32 + ww] = d_mask[b][rowOf[s]][ww];
    }
    __syncthreads();

    if (t < 32) {
        int lane = t;
        int kept = 0;
        for (int w = 0; w < NW1 && kept < PROP; ++w) {
            unsigned long long remWord = remv[w];
            unsigned long long rw = rowAnyS[w];
            for (int bit = 0; bit < 64; ++bit) {
                if (!((remWord >> bit) & 1ull)) {
                    int i = w * 64 + bit;
                    if (lane == 0) keepIdx[kept] = i;
                    kept++;
                    if (kept == PROP) break;
                    if ((rw >> bit) & 1ull) {
                        short s = slotv[i];
                        const unsigned long long* row =
                            (s >= 0) ? &cache[(int)s * 32] : d_mask[b][i];
                        for (int ww = w + lane; ww < NW1; ww += 32)
                            remv[ww] |= row[ww];
                        __syncwarp();
                        remWord = remv[w];
                    }
                }
            }
        }
        if (lane == 0) {
            keptS = kept;
            if (kept == PROP) d_done[b] = 1;
        }
    }
    __syncthreads();

    if (keptS == PROP) {
        float4* o4 = (float4*)(out + (size_t)b * PROP * 4);
        for (int r = t; r < PROP; r += 1024)
            o4[r] = d_boxes[b][keepIdx[r]];
    }
}

// ---------------- phase-2 scan (fallback, gated per batch) --------------------
__global__ void k_scan2(float* __restrict__ out) {
    int b = blockIdx.x, lane = threadIdx.x;          // 32 threads
    if (d_done[b]) return;
    __shared__ unsigned long long remv[NW];
    __shared__ unsigned long long rowAnyS[NW];
    __shared__ int keepIdx[PROP];
    for (int w = lane; w < NW; w += 32) {
        remv[w] = 0ull;
        rowAnyS[w] = d_rowAny[b][w];
    }
    __syncwarp();

    int kept = 0;
    for (int w = 0; w < NW && kept < PROP; ++w) {
        unsigned long long remWord = remv[w];
        unsigned long long rw = rowAnyS[w];
        int lim = (w * 64 + 64 <= KK) ? 64 : (KK - w * 64);
        for (int bit = 0; bit < lim; ++bit) {
            if (!((remWord >> bit) & 1ull)) {
                int i = w * 64 + bit;
                if (lane == 0) keepIdx[kept] = i;
                kept++;
                if (kept == PROP) break;
                if ((rw >> bit) & 1ull) {
                    const unsigned long long* row = d_mask[b][i];
                    for (int ww = w + lane; ww < NW; ww += 32)
                        remv[ww] |= row[ww];
                    __syncwarp();
                    remWord = remv[w];
                }
            }
        }
    }
    __syncwarp();

    int total = kept;
    float4* o4 = (float4*)(out + (size_t)b * PROP * 4);
    for (int r = lane; r < PROP; r += 32) {
        float4 v = make_float4(0.f, 0.f, 0.f, 0.f);
        if (r < total) v = d_boxes[b][keepIdx[r]];
        o4[r] = v;
    }
}

// ---------------- launch ----------------
extern "C" void kernel_launch(void* const* d_in, const int* in_sizes, int n_in,
                              void* d_out, int out_size) {
    const float* scores  = (const float*)d_in[0];
    const float* deltas  = (const float*)d_in[1];
    const float* anchors = (const float*)d_in[2];
    float* out = (float*)d_out;

    cudaFuncSetAttribute(k_scan1, cudaFuncAttributeMaxDynamicSharedMemorySize,
                         RCAP * 32 * (int)sizeof(unsigned long long));

    const float4* s4 = (const float4*)scores;
    int nq = BB * NN / 4;

    k_init    <<<(BB * 65536 + 255) / 256, 256>>>();
    k_hist    <<<(nq + 255) / 256, 256>>>(s4);
    k_base    <<<BB, 1024>>>();
    k_scatter <<<(nq + 255) / 256, 256>>>(s4);
    k_groupsort<<<dim3(64, BB), 1024>>>();
    k_box     <<<(BB * NPAD + 255) / 256, 256>>>(deltas, anchors);
    k_mask1   <<<dim3(NW1, NW1, BB), 64>>>();
    k_scan1   <<<BB, 1024, RCAP * 32 * (int)sizeof(unsigned long long)>>>(out);
    k_mask2   <<<dim3(NW, NW, BB), 64>>>();
    k_scan2   <<<BB, 32>>>(out);
}

// round 9
// speedup vs baseline: 4.8447x; 1.6046x over previous
#include <cuda_runtime.h>
#include <math.h>

#define BB 4
#define NN 262144
#define KK 6000
#define NPAD 6016            // 94 * 64
#define NW 94                // 64-bit words per full row
#define SCAPACITY 8192       // sorted-candidate capacity
#define PROP 1000
#define THR 0.7f
#define C1 1536              // phase-1 NMS window (rows/cols)
#define NW1 24               // 64-bit words for phase-1 row
#define GCAP 2048            // per-prefix-bin group sort capacity
#define RCAP 256             // cached suppressor rows in scan1

// ---------------- scratch (static device globals; no allocation) ----------------
__device__ unsigned int       d_hist[BB][65536];
__device__ int                d_base[BB][65536];
__device__ unsigned int       d_chunkSum[BB][64];
__device__ unsigned int       d_chunkBase[BB][64];
__device__ int                d_P[BB];
__device__ unsigned long long d_sorted[BB][SCAPACITY];
__device__ float4             d_boxes[BB][NPAD];
__device__ unsigned long long d_mask[BB][NPAD][NW];
__device__ unsigned long long d_rowAny[BB][NW];
__device__ int                d_done[BB];

// ---------------- init: zero per-launch state ----------------
__global__ void k_init() {
    int i = blockIdx.x * blockDim.x + threadIdx.x;
    if (i < BB * 65536) ((unsigned int*)d_hist)[i] = 0u;
    if (i < BB)        { d_P[i] = 0; d_done[i] = 0; }
    if (i < BB * NW)     ((unsigned long long*)d_rowAny)[i] = 0ull;
}

// ---------------- histogram of fg-score top-16 bits (float4 vectorized) --------
__global__ void k_hist(const float4* __restrict__ s4) {
    int t = blockIdx.x * blockDim.x + threadIdx.x;   // over BB*NN/4
    if (t >= BB * NN / 4) return;
    float4 a = s4[2 * t], c = s4[2 * t + 1];         // 4 [bg,fg] pairs
    int b = t >> 16;                                 // (4t) >> 18
    atomicAdd(&d_hist[b][__float_as_uint(a.y) >> 16], 1u);
    atomicAdd(&d_hist[b][__float_as_uint(a.w) >> 16], 1u);
    atomicAdd(&d_hist[b][__float_as_uint(c.y) >> 16], 1u);
    atomicAdd(&d_hist[b][__float_as_uint(c.w) >> 16], 1u);
}

// ---------------- base pass A: per-chunk (1024-bin) sums -----------------------
__global__ void k_base_a() {
    int c = blockIdx.x, b = blockIdx.y, t = threadIdx.x;   // 256 threads, 4 bins each
    __shared__ unsigned int red[256];
    const unsigned int* h = d_hist[b] + c * 1024 + t * 4;
    unsigned int s = h[0] + h[1] + h[2] + h[3];
    red[t] = s;
    __syncthreads();
    for (int off = 128; off > 0; off >>= 1) {
        if (t < off) red[t] += red[t + off];
        __syncthreads();
    }
    if (t == 0) d_chunkSum[b][c] = red[0];
}

// ---------------- base pass B: suffix-exclusive scan of 64 chunk sums ----------
__global__ void k_base_b() {
    int b = blockIdx.x, t = threadIdx.x;             // 64 threads
    __shared__ unsigned int v[64];
    v[t] = d_chunkSum[b][t];
    __syncthreads();
    unsigned int acc = 0;
    for (int c = t + 1; c < 64; ++c) acc += v[c];    // count strictly above my chunk
    d_chunkBase[b][t] = acc;
}

// ---------------- base pass C: per-bin suffix bases + threshold ----------------
__global__ void k_base_c() {
    int c = blockIdx.x, b = blockIdx.y, t = threadIdx.x;   // 256 threads, 4 bins each
    __shared__ unsigned int part[256];
    const unsigned int* h = d_hist[b] + c * 1024;
    int t4 = t * 4;
    unsigned int mySum = h[t4] + h[t4 + 1] + h[t4 + 2] + h[t4 + 3];
    part[t] = mySum;
    __syncthreads();
    // inclusive suffix scan over 256 thread sums
    for (int off = 1; off < 256; off <<= 1) {
        unsigned int add = (t + off < 256) ? part[t + off] : 0u;
        __syncthreads();
        part[t] += add;
        __syncthreads();
    }
    unsigned int acc = d_chunkBase[b][c] + (part[t] - mySum);  // strictly above my bins
    int bestBin = -1;
    #pragma unroll
    for (int kk = 3; kk >= 0; --kk) {
        int bin = c * 1024 + t4 + kk;
        unsigned int hv = h[t4 + kk];
        d_base[b][bin] = (int)acc;
        if (bestBin < 0 && acc + hv >= (unsigned)KK) bestBin = bin;
        acc += hv;
    }
    if (bestBin >= 0) atomicMax(&d_P[b], bestBin);
}

// ---------------- scatter candidates into exact bin slot ranges ----------------
__global__ void k_scatter(const float4* __restrict__ s4) {
    int t = blockIdx.x * blockDim.x + threadIdx.x;   // over BB*NN/4
    if (t >= BB * NN / 4) return;
    float4 a = s4[2 * t], c = s4[2 * t + 1];
    int b = t >> 16;
    int P = d_P[b];
    int pair0 = (4 * t) & (NN - 1);
    float fg[4] = {a.y, a.w, c.y, c.w};
    #pragma unroll
    for (int j = 0; j < 4; ++j) {
        unsigned int bits = __float_as_uint(fg[j]);
        if ((int)(bits >> 16) >= P) {
            int pos = atomicAdd(&d_base[b][bits >> 16], 1);
            if (pos < SCAPACITY)
                d_sorted[b][pos] = ((unsigned long long)bits << 32) |
                                   (unsigned long long)(0xFFFFFFFFu - (unsigned)(pair0 + j));
        }
    }
}

// ---------------- per-bin group sort (bitonic 2048, one block per active bin) --
__global__ void k_groupsort() {
    __shared__ unsigned long long skey[GCAP];        // 16 KB
    int b = blockIdx.y;
    int bin = d_P[b] + blockIdx.x;
    if (bin > 65535) return;
    int hv = (int)d_hist[b][bin];
    if (hv <= 1) return;
    int end = d_base[b][bin];                        // post-scatter = orig + hist
    int start = end - hv;
    int g = hv < GCAP ? hv : GCAP;
    if (end > SCAPACITY) end = SCAPACITY;
    int t = threadIdx.x;                             // 1024 threads
    for (int i = t; i < GCAP; i += 1024)
        skey[i] = (i < g && start + i < SCAPACITY) ? d_sorted[b][start + i] : 0ull;
    __syncthreads();
    for (int k = 2; k <= GCAP; k <<= 1) {
        for (int j = k >> 1; j > 0; j >>= 1) {
            for (int i = t; i < GCAP; i += 1024) {
                int p = i ^ j;
                if (p > i) {
                    unsigned long long x = skey[i], y = skey[p];
                    bool up = (i & k) == 0;          // descending
                    if (up ? (x < y) : (x > y)) { skey[i] = y; skey[p] = x; }
                }
            }
            __syncthreads();
        }
    }
    for (int i = t; i < g; i += 1024)
        if (start + i < SCAPACITY) d_sorted[b][start + i] = skey[i];
}

// ---------------- decode sorted keys -> boxes (fully parallel) -----------------
__global__ void k_box(const float* __restrict__ deltas,
                      const float* __restrict__ anchors) {
    int i = blockIdx.x * blockDim.x + threadIdx.x;   // over BB*NPAD
    if (i >= BB * NPAD) return;
    int b = i / NPAD;
    int r = i - b * NPAD;
    float4 box = make_float4(0.f, 0.f, 0.f, 0.f);
    if (r < KK) {
        unsigned long long key = d_sorted[b][r];
        unsigned int n = 0xFFFFFFFFu - (unsigned int)(key & 0xFFFFFFFFull);
        const float4* anc4 = (const float4*)anchors;
        const float4* del4 = (const float4*)deltas;
        float4 a4 = anc4[(size_t)b * NN + n];
        float4 dd = del4[(size_t)b * NN + n];
        float d0 = __fmul_rn(dd.x, 0.1f);
        float d1 = __fmul_rn(dd.y, 0.1f);
        float d2 = __fmul_rn(dd.z, 0.2f);
        float d3 = __fmul_rn(dd.w, 0.2f);
        float w  = __fsub_rn(a4.z, a4.x);
        float h  = __fsub_rn(a4.w, a4.y);
        float cx = __fadd_rn(a4.x, __fmul_rn(0.5f, w));
        float cy = __fadd_rn(a4.y, __fmul_rn(0.5f, h));
        cx = __fadd_rn(cx, __fmul_rn(d0, w));
        cy = __fadd_rn(cy, __fmul_rn(d1, h));
        w  = __fmul_rn(w, (float)exp((double)d2));
        h  = __fmul_rn(h, (float)exp((double)d3));
        float x1 = __fsub_rn(cx, __fmul_rn(0.5f, w));
        float y1 = __fsub_rn(cy, __fmul_rn(0.5f, h));
        float x2 = __fadd_rn(cx, __fmul_rn(0.5f, w));
        float y2 = __fadd_rn(cy, __fmul_rn(0.5f, h));
        box.x = fminf(fmaxf(x1, 0.f), 1.f);
        box.y = fminf(fmaxf(y1, 0.f), 1.f);
        box.z = fminf(fmaxf(x2, 0.f), 1.f);
        box.w = fminf(fmaxf(y2, 0.f), 1.f);
    }
    d_boxes[b][r] = box;
}

// ---------------- shared IoU block body (division-filtered, exact) -------------
__device__ __forceinline__ void mask_block_body(int cb, int rb, int b) {
    __shared__ float4 cbox[64];
    __shared__ float  cArea[64];
    int t = threadIdx.x;
    float4 c4 = d_boxes[b][cb * 64 + t];
    cbox[t] = c4;
    cArea[t] = __fmul_rn(__fsub_rn(c4.z, c4.x), __fsub_rn(c4.w, c4.y));
    __syncthreads();
    int i = rb * 64 + t;
    float4 bx = d_boxes[b][i];
    float areaI = __fmul_rn(__fsub_rn(bx.z, bx.x), __fsub_rn(bx.w, bx.y));
    bool diag = (cb == rb);
    unsigned long long bits = 0ull;
    #pragma unroll 4
    for (int c = 0; c < 64; ++c) {
        if (!diag || c > t) {
            float4 o = cbox[c];
            float lx = fmaxf(bx.x, o.x), ly = fmaxf(bx.y, o.y);
            float rx = fminf(bx.z, o.z), ry = fminf(bx.w, o.w);
            float iw = fmaxf(__fsub_rn(rx, lx), 0.f);
            float ih = fmaxf(__fsub_rn(ry, ly), 0.f);
            float inter = __fmul_rn(iw, ih);
            float denom = __fadd_rn(__fsub_rn(__fadd_rn(areaI, cArea[c]), inter), 1e-12f);
            // conservative filter: true ratio <= 0.6901 can never round to > 0.7,
            // so the exact division is only needed when inter > 0.69*denom.
            if (inter > __fmul_rn(0.69f, denom)) {
                float iou = __fdiv_rn(inter, denom);
                if (iou > THR) bits |= (1ull << c);
            }
        }
    }
    d_mask[b][i][cb] = bits;
    if (bits) atomicOr(&d_rowAny[b][i >> 6], 1ull << (i & 63));
}

// ---------------- phase-1 mask: top C1 x C1 triangle --------------------------
__global__ void k_mask1() {
    int cb = blockIdx.x, rb = blockIdx.y, b = blockIdx.z;
    if (cb < rb) return;
    mask_block_body(cb, rb, b);
}

// ---------------- phase-2 mask (fallback, gated per batch) --------------------
__global__ void k_mask2() {
    int cb = blockIdx.x, rb = blockIdx.y, b = blockIdx.z;
    if (d_done[b]) return;
    if (cb < rb) return;
    if (cb < NW1 && rb < NW1) return;   // phase 1 already wrote this region
    mask_block_body(cb, rb, b);
}

// ---------------- phase-1 scan: cache suppressor rows, then greedy NMS --------
__global__ void k_scan1(float* __restrict__ out) {
    int b = blockIdx.x, t = threadIdx.x;             // 1024 threads
    extern __shared__ unsigned long long cache[];    // RCAP*NW1 words = 48 KB
    __shared__ unsigned long long remv[NW1];
    __shared__ unsigned long long rowAnyS[NW1];
    __shared__ int keepIdx[PROP];
    __shared__ short slotv[C1];
    __shared__ int rowOf[RCAP];
    __shared__ int nsup, keptS;
    if (t == 0) { nsup = 0; keptS = 0; }
    if (t < NW1) { remv[t] = 0ull; rowAnyS[t] = d_rowAny[b][t]; }
    __syncthreads();

    // compact suppressor rows
    for (int i = t; i < C1; i += 1024) {
        short s = -1;
        if ((rowAnyS[i >> 6] >> (i & 63)) & 1ull) {
            int p = atomicAdd(&nsup, 1);
            if (p < RCAP) { s = (short)p; rowOf[p] = i; }
        }
        slotv[i] = s;
    }
    __syncthreads();

    // bulk-load cached rows (high MLP)
    int ns = nsup < RCAP ? nsup : RCAP;
    for (int w = t; w < ns * NW1; w += 1024) {
        int s = w / NW1, ww = w - s * NW1;
        cache[s * NW1 + ww] = d_mask[b][rowOf[s]][ww];
    }
    __syncthreads();

    if (t < 32) {
        int lane = t;
        int kept = 0;
        for (int w = 0; w < NW1 && kept < PROP; ++w) {
            unsigned long long remWord = remv[w];
            unsigned long long rw = rowAnyS[w];
            for (int bit = 0; bit < 64; ++bit) {
                if (!((remWord >> bit) & 1ull)) {
                    int i = w * 64 + bit;
                    if (lane == 0) keepIdx[kept] = i;
                    kept++;
                    if (kept == PROP) break;
                    if ((rw >> bit) & 1ull) {
                        short s = slotv[i];
                        const unsigned long long* row =
                            (s >= 0) ? &cache[(int)s * NW1] : d_mask[b][i];
                        for (int ww = w + lane; ww < NW1; ww += 32)
                            remv[ww] |= row[ww];
                        __syncwarp();
                        remWord = remv[w];
                    }
                }
            }
        }
        if (lane == 0) {
            keptS = kept;
            if (kept == PROP) d_done[b] = 1;
        }
    }
    __syncthreads();

    if (keptS == PROP) {
        float4* o4 = (float4*)(out + (size_t)b * PROP * 4);
        for (int r = t; r < PROP; r += 1024)
            o4[r] = d_boxes[b][keepIdx[r]];
    }
}

// ---------------- phase-2 scan (fallback, gated per batch) --------------------
__global__ void k_scan2(float* __restrict__ out) {
    int b = blockIdx.x, lane = threadIdx.x;          // 32 threads
    if (d_done[b]) return;
    __shared__ unsigned long long remv[NW];
    __shared__ unsigned long long rowAnyS[NW];
    __shared__ int keepIdx[PROP];
    for (int w = lane; w < NW; w += 32) {
        remv[w] = 0ull;
        rowAnyS[w] = d_rowAny[b][w];
    }
    __syncwarp();

    int kept = 0;
    for (int w = 0; w < NW && kept < PROP; ++w) {
        unsigned long long remWord = remv[w];
        unsigned long long rw = rowAnyS[w];
        int lim = (w * 64 + 64 <= KK) ? 64 : (KK - w * 64);
        for (int bit = 0; bit < lim; ++bit) {
            if (!((remWord >> bit) & 1ull)) {
                int i = w * 64 + bit;
                if (lane == 0) keepIdx[kept] = i;
                kept++;
                if (kept == PROP) break;
                if ((rw >> bit) & 1ull) {
                    const unsigned long long* row = d_mask[b][i];
                    for (int ww = w + lane; ww < NW; ww += 32)
                        remv[ww] |= row[ww];
                    __syncwarp();
                    remWord = remv[w];
                }
            }
        }
    }
    __syncwarp();

    int total = kept;
    float4* o4 = (float4*)(out + (size_t)b * PROP * 4);
    for (int r = lane; r < PROP; r += 32) {
        float4 v = make_float4(0.f, 0.f, 0.f, 0.f);
        if (r < total) v = d_boxes[b][keepIdx[r]];
        o4[r] = v;
    }
}

// ---------------- launch ----------------
extern "C" void kernel_launch(void* const* d_in, const int* in_sizes, int n_in,
                              void* d_out, int out_size) {
    const float* scores  = (const float*)d_in[0];
    const float* deltas  = (const float*)d_in[1];
    const float* anchors = (const float*)d_in[2];
    float* out = (float*)d_out;

    cudaFuncSetAttribute(k_scan1, cudaFuncAttributeMaxDynamicSharedMemorySize,
                         RCAP * NW1 * (int)sizeof(unsigned long long));

    const float4* s4 = (const float4*)scores;
    int nq = BB * NN / 4;

    k_init    <<<(BB * 65536 + 255) / 256, 256>>>();
    k_hist    <<<(nq + 255) / 256, 256>>>(s4);
    k_base_a  <<<dim3(64, BB), 256>>>();
    k_base_b  <<<BB, 64>>>();
    k_base_c  <<<dim3(64, BB), 256>>>();
    k_scatter <<<(nq + 255) / 256, 256>>>(s4);
    k_groupsort<<<dim3(64, BB), 1024>>>();
    k_box     <<<(BB * NPAD + 255) / 256, 256>>>(deltas, anchors);
    k_mask1   <<<dim3(NW1, NW1, BB), 64>>>();
    k_scan1   <<<BB, 1024, RCAP * NW1 * (int)sizeof(unsigned long long)>>>(out);
    k_mask2   <<<dim3(NW, NW, BB), 64>>>();
    k_scan2   <<<BB, 32>>>(out);
}